// round 7
// baseline (speedup 1.0000x reference)
#include <cuda_runtime.h>
#include <cuda_fp16.h>
#include <cstdint>

#define N_C    16
#define DIN    1024
#define HID    128
#define TILE_M 128
#define KC     64
#define NCHUNK (DIN / KC)   // 16

// ---------------- device scratch ----------------
__device__ __align__(1024) __half g_xh [67108864];        // 65536*1024 fp16
__device__ __align__(1024) __half g_w1t[N_C * HID * DIN]; // [c][h][d] K-major
__device__ __align__(1024) __half g_w2t[N_C * HID * HID]; // [c][ho][hi] K-major

// ---------------- smem: 3 ring slots of 32KB (A @+0, B @+16K) + vectors ----------------
#define SLOT(s)    ((uint32_t)(s) * 32768u)     // 0, 32768, 65536
#define OFF_B1S    98304u
#define OFF_B2S    98816u
#define OFF_W3S    99328u
#define OFF_ACC    99840u
#define SMEM_TOTAL 100352u

#define SWZ(bo) ((bo) ^ (((bo) >> 3) & 0x70))

__device__ __forceinline__ uint32_t smem_u32(const void* p) {
    uint32_t a;
    asm("{ .reg .u64 t; cvta.to.shared.u64 t, %1; cvt.u32.u64 %0, t; }" : "=r"(a) : "l"(p));
    return a;
}

// cp.async a [128 x 128B] tile into swizzled smem; 256 threads, 16B each, 4 iters
__device__ __forceinline__ void cpa_tile(uint32_t soff_abs, const char* g,
                                         int stride_bytes, int tid) {
#pragma unroll
    for (int it = 0; it < 4; ++it) {
        int u = it * 256 + tid;
        int r = u >> 3, w = u & 7;
        uint32_t d = soff_abs + SWZ((uint32_t)(r * 128 + w * 16));
        const char* src = g + (size_t)r * stride_bytes + w * 16;
        asm volatile("cp.async.cg.shared.global [%0], [%1], 16;" :: "r"(d), "l"(src));
    }
}
#define CPA_COMMIT() asm volatile("cp.async.commit_group;" ::: "memory")
#define CPA_WAIT(n)  asm volatile("cp.async.wait_group %0;" :: "n"(n) : "memory")

__device__ __forceinline__ void ldmA(uint32_t addr, uint32_t* f) {
    asm volatile("ldmatrix.sync.aligned.m8n8.x4.shared.b16 {%0,%1,%2,%3}, [%4];"
                 : "=r"(f[0]), "=r"(f[1]), "=r"(f[2]), "=r"(f[3]) : "r"(addr));
}
__device__ __forceinline__ void ldmB4(uint32_t addr, uint32_t* f) {
    asm volatile("ldmatrix.sync.aligned.m8n8.x4.shared.b16 {%0,%1,%2,%3}, [%4];"
                 : "=r"(f[0]), "=r"(f[1]), "=r"(f[2]), "=r"(f[3]) : "r"(addr));
}
__device__ __forceinline__ void mma16816(float* c, const uint32_t* a, const uint32_t* b) {
    asm volatile(
        "mma.sync.aligned.m16n8k16.row.col.f32.f16.f16.f32 "
        "{%0,%1,%2,%3}, {%4,%5,%6,%7}, {%8,%9}, {%0,%1,%2,%3};"
        : "+f"(c[0]), "+f"(c[1]), "+f"(c[2]), "+f"(c[3])
        : "r"(a[0]), "r"(a[1]), "r"(a[2]), "r"(a[3]), "r"(b[0]), "r"(b[1]));
}

__device__ __forceinline__ uint32_t b4_addr(uint32_t sB, int ks, int q, int lane, int wn) {
    int grp = lane >> 3;
    int row = wn * 32 + (2 * q + (grp >> 1)) * 8 + (lane & 7);
    uint32_t bo = (uint32_t)(row * 128 + ks * 32 + ((grp & 1) << 4));
    return sB + SWZ(bo);
}

// one 64-wide K chunk; per-warp ks rotation (swizzle on FULL offset)
__device__ __forceinline__ void gemm64(uint32_t sA, uint32_t sB,
                                       float acc[4][4][4], int lane, int wm, int wn,
                                       int rot) {
#pragma unroll
    for (int k2 = 0; k2 < 4; ++k2) {
        int ks = (k2 + rot) & 3;
        uint32_t a[4][4], b[4][2];
#pragma unroll
        for (int mt = 0; mt < 4; ++mt) {
            int row = wm * 64 + mt * 16 + (lane & 15);
            uint32_t bo = (uint32_t)(row * 128 + ks * 32 + ((lane >> 4) << 4));
            ldmA(sA + SWZ(bo), a[mt]);
        }
#pragma unroll
        for (int q = 0; q < 2; ++q)
            ldmB4(b4_addr(sB, ks, q, lane, wn), &b[2 * q][0]);
#pragma unroll
        for (int mt = 0; mt < 4; ++mt)
#pragma unroll
            for (int nt = 0; nt < 4; ++nt)
                mma16816(acc[mt][nt], a[mt], b[nt]);
    }
}

// convert one 64-col slice s of this CTA's 128 rows: fp32 -> fp16 global
__device__ __forceinline__ void conv_slice(const float* __restrict__ xf32,
                                           int row0, int s, int tid) {
    const float4* src = (const float4*)(xf32 + (size_t)row0 * DIN);
    __half* dstbase = g_xh + (size_t)row0 * DIN;
#pragma unroll
    for (int it = 0; it < 8; ++it) {
        int u = it * 256 + tid;          // 0..2047: 128 rows x 16 float4
        int row = u >> 4, seg = u & 15;
        float4 v = src[row * (DIN / 4) + s * 16 + seg];
        __half2 h0 = __floats2half2_rn(v.x, v.y);
        __half2 h1 = __floats2half2_rn(v.z, v.w);
        uint2 pk;
        pk.x = *(uint32_t*)&h0;
        pk.y = *(uint32_t*)&h1;
        *(uint2*)(dstbase + (size_t)row * DIN + s * 64 + seg * 4) = pk;
    }
}

// ---------------- prep kernel (weights only) ----------------
__global__ void prep_w(const float* __restrict__ W1, const float* __restrict__ W2) {
    int i = blockIdx.x * 256 + threadIdx.x;
    const int n1 = N_C * DIN * HID;
    if (i < n1) {
        int c = i / (DIN * HID);
        int rem = i % (DIN * HID);
        int h = rem / DIN;
        int d = rem % DIN;
        g_w1t[i] = __float2half_rn(W1[(c * DIN + d) * HID + h]);
    } else {
        int k = i - n1;
        if (k < N_C * HID * HID) {
            int c = k / (HID * HID);
            int rem = k % (HID * HID);
            int ho = rem / HID;
            int hi = rem % HID;
            g_w2t[k] = __float2half_rn(W2[(c * HID + hi) * HID + ho]);
        }
    }
}

// ---------------- main fused MLP kernel ----------------
__global__ void __launch_bounds__(256, 2) mlp_main(
    const float* __restrict__ xf32,
    const float* __restrict__ b1, const float* __restrict__ b2,
    const float* __restrict__ W3, const float* __restrict__ b3,
    float* __restrict__ out) {
    extern __shared__ char smem[];
    const uint32_t sbase = smem_u32(smem);
    const int tid  = threadIdx.x;
    const int lane = tid & 31;
    const int wid  = tid >> 5;
    const int wm   = wid >> 2;
    const int wn   = wid & 3;
    const int rot  = wid & 3;
    const int row0 = blockIdx.x * TILE_M;

    float* b1s    = (float*)(smem + OFF_B1S);
    float* b2s    = (float*)(smem + OFF_B2S);
    float* w3s    = (float*)(smem + OFF_W3S);
    float* rowacc = (float*)(smem + OFF_ACC);

    float acc[4][4][4];
    const char* xg = (const char*)(g_xh + (size_t)row0 * DIN);

    // prologue: convert slices 0..2, then issue channel-0 chunks 0,1 (2 groups)
    conv_slice(xf32, row0, 0, tid);
    conv_slice(xf32, row0, 1, tid);
    conv_slice(xf32, row0, 2, tid);
    __syncthreads();
    cpa_tile(sbase + SLOT(0), xg, DIN * 2, tid);
    cpa_tile(sbase + SLOT(0) + 16384u, (const char*)g_w1t, DIN * 2, tid);
    CPA_COMMIT();
    cpa_tile(sbase + SLOT(1), xg + (size_t)KC * 2, DIN * 2, tid);
    cpa_tile(sbase + SLOT(1) + 16384u, (const char*)g_w1t + (size_t)KC * 2, DIN * 2, tid);
    CPA_COMMIT();

#pragma unroll 1
    for (int c = 0; c < N_C; ++c) {
        if (tid < HID) {
            b1s[tid] = b1[c * HID + tid];
            b2s[tid] = b2[c * HID + tid];
            w3s[tid] = W3[c * HID + tid];
            rowacc[tid] = 0.f;
        }
#pragma unroll
        for (int mt = 0; mt < 4; ++mt)
#pragma unroll
            for (int nt = 0; nt < 4; ++nt)
#pragma unroll
                for (int i = 0; i < 4; ++i) acc[mt][nt][i] = 0.f;

        const char* w1c = (const char*)(g_w1t + (size_t)c * HID * DIN);

        // ==== GEMM1: 3-slot ring, ONE sync per chunk, issue-before-wait ====
#pragma unroll 1
        for (int j = 0; j < NCHUNK; ++j) {
            __syncthreads();   // gemm j-1 done everywhere; slot (j+2)%3 reusable
            if (j + 2 < NCHUNK) {
                uint32_t s = SLOT((j + 2) % 3);
                cpa_tile(sbase + s, xg + (size_t)(j + 2) * KC * 2, DIN * 2, tid);
                cpa_tile(sbase + s + 16384u, w1c + (size_t)(j + 2) * KC * 2, DIN * 2, tid);
                CPA_COMMIT();
            }
            if (c == 0 && j + 3 < NCHUNK) conv_slice(xf32, row0, j + 3, tid);
            if (j < NCHUNK - 2)      CPA_WAIT(2);
            else if (j == NCHUNK - 2) CPA_WAIT(1);
            else                      CPA_WAIT(0);
            uint32_t s = SLOT(j % 3);
            gemm64(sbase + s, sbase + s + 16384u, acc, lane, wm, wn, rot);
        }
        __syncthreads();   // gemm 15 done; all slots free

        // issue W2 (slot 2) + next channel chunk 0 (slot 0) — one group
        {
            const char* w2c = (const char*)(g_w2t + (size_t)c * HID * HID);
            cpa_tile(sbase + SLOT(2), w2c, HID * 2, tid);
            cpa_tile(sbase + SLOT(2) + 16384u, w2c + (size_t)KC * 2, HID * 2, tid);
            if (c < N_C - 1) {
                const char* w1n = (const char*)(g_w1t + (size_t)(c + 1) * HID * DIN);
                cpa_tile(sbase + SLOT(0), xg, DIN * 2, tid);
                cpa_tile(sbase + SLOT(0) + 16384u, w1n, DIN * 2, tid);
            }
            CPA_COMMIT();
        }

        // ==== epilogue 1: relu(acc + b1) -> fp16 h1 into slot 1 ====
#pragma unroll
        for (int mt = 0; mt < 4; ++mt) {
            int r1 = wm * 64 + mt * 16 + (lane >> 2);
#pragma unroll
            for (int nt = 0; nt < 4; ++nt) {
                int n = wn * 32 + nt * 8 + (lane & 3) * 2;
                uint32_t chb = SLOT(1) + (uint32_t)(n >> 6) * 16384u;
                uint32_t nc = (uint32_t)(n & 63);
                float* cc = acc[mt][nt];
                __half2 h0 = __floats2half2_rn(fmaxf(cc[0] + b1s[n], 0.f),
                                               fmaxf(cc[1] + b1s[n + 1], 0.f));
                __half2 h1v = __floats2half2_rn(fmaxf(cc[2] + b1s[n], 0.f),
                                                fmaxf(cc[3] + b1s[n + 1], 0.f));
                *(__half2*)(smem + chb + SWZ((uint32_t)r1 * 128u + nc * 2u)) = h0;
                *(__half2*)(smem + chb + SWZ((uint32_t)(r1 + 8) * 128u + nc * 2u)) = h1v;
            }
        }
        CPA_WAIT(0);
        __syncthreads();   // h1 + W2 + next chunk0 ready

        // ==== GEMM2: h1 (slot1) @ W2^T (slot2) ====
#pragma unroll
        for (int mt = 0; mt < 4; ++mt)
#pragma unroll
            for (int nt = 0; nt < 4; ++nt)
#pragma unroll
                for (int i = 0; i < 4; ++i) acc[mt][nt][i] = 0.f;

        gemm64(sbase + SLOT(1),          sbase + SLOT(2),          acc, lane, wm, wn, rot);
        gemm64(sbase + SLOT(1) + 16384u, sbase + SLOT(2) + 16384u, acc, lane, wm, wn, rot);
        __syncthreads();   // slots 1,2 free

        // issue next channel chunk 1 (slot 1) — overlaps epilogue 2
        if (c < N_C - 1) {
            const char* w1n = (const char*)(g_w1t + (size_t)(c + 1) * HID * DIN);
            cpa_tile(sbase + SLOT(1), xg + (size_t)KC * 2, DIN * 2, tid);
            cpa_tile(sbase + SLOT(1) + 16384u, w1n + (size_t)KC * 2, DIN * 2, tid);
            CPA_COMMIT();
        }

        // ==== epilogue 2: out = relu(acc + b2) . W3 + b3 ====
#pragma unroll
        for (int mt = 0; mt < 4; ++mt) {
            float p1 = 0.f, p2 = 0.f;
#pragma unroll
            for (int nt = 0; nt < 4; ++nt) {
                int n = wn * 32 + nt * 8 + (lane & 3) * 2;
                float* cc = acc[mt][nt];
                float w0 = w3s[n], w1v = w3s[n + 1];
                float c2a = b2s[n], c2b = b2s[n + 1];
                p1 += fmaxf(cc[0] + c2a, 0.f) * w0 + fmaxf(cc[1] + c2b, 0.f) * w1v;
                p2 += fmaxf(cc[2] + c2a, 0.f) * w0 + fmaxf(cc[3] + c2b, 0.f) * w1v;
            }
            p1 += __shfl_xor_sync(0xFFFFFFFFu, p1, 1);
            p1 += __shfl_xor_sync(0xFFFFFFFFu, p1, 2);
            p2 += __shfl_xor_sync(0xFFFFFFFFu, p2, 1);
            p2 += __shfl_xor_sync(0xFFFFFFFFu, p2, 2);
            if ((lane & 3) == 0) {
                int r = wm * 64 + mt * 16 + (lane >> 2);
                atomicAdd(&rowacc[r], p1);
                atomicAdd(&rowacc[r + 8], p2);
            }
        }
        __syncthreads();
        if (tid < TILE_M)
            out[(size_t)(row0 + tid) * N_C + c] = rowacc[tid] + b3[c];
        __syncthreads();   // protect smem vectors before next channel rewrites
    }
}

// ---------------- launch ----------------
extern "C" void kernel_launch(void* const* d_in, const int* in_sizes, int n_in,
                              void* d_out, int out_size) {
    const float* x  = (const float*)d_in[0];
    const float* W1 = (const float*)d_in[1];
    const float* b1 = (const float*)d_in[2];
    const float* W2 = (const float*)d_in[3];
    const float* b2 = (const float*)d_in[4];
    const float* W3 = (const float*)d_in[5];
    const float* b3 = (const float*)d_in[6];
    float* out = (float*)d_out;

    const int npts = in_sizes[0] / DIN;               // 65536
    const int wtot = N_C * DIN * HID + N_C * HID * HID;
    prep_w<<<(wtot + 255) / 256, 256>>>(W1, W2);

    cudaFuncSetAttribute(mlp_main, cudaFuncAttributeMaxDynamicSharedMemorySize, SMEM_TOTAL);
    mlp_main<<<npts / TILE_M, 256, SMEM_TOTAL>>>(x, b1, b2, W3, b3, out);
}

// round 8
// speedup vs baseline: 1.0078x; 1.0078x over previous
#include <cuda_runtime.h>
#include <cuda_fp16.h>
#include <cstdint>

#define N_C    16
#define DIN    1024
#define HID    128
#define TILE_M 128
#define KC     64
#define NCHUNK (DIN / KC)   // 16

// ---------------- device scratch ----------------
__device__ __align__(1024) __half g_xh [67108864];        // 65536*1024 fp16
__device__ __align__(1024) __half g_w1t[N_C * HID * DIN]; // [c][h][d] K-major
__device__ __align__(1024) __half g_w2t[N_C * HID * HID]; // [c][ho][hi] K-major

// ---------------- smem layout ----------------
#define OFF_SA(s)  ((uint32_t)(s) * 16384u)            // 0, 16384
#define OFF_SB(s)  (32768u + (uint32_t)(s) * 16384u)   // 32768, 49152
#define OFF_H1     65536u                              // 32KB: chunk0 @+0, chunk1 @+16384
#define OFF_B1S    98304u
#define OFF_B2S    98816u
#define OFF_W3S    99328u
#define OFF_ACC    99840u
#define SMEM_TOTAL 100352u

#define SWZ(bo) ((bo) ^ (((bo) >> 3) & 0x70))

__device__ __forceinline__ uint32_t smem_u32(const void* p) {
    uint32_t a;
    asm("{ .reg .u64 t; cvta.to.shared.u64 t, %1; cvt.u32.u64 %0, t; }" : "=r"(a) : "l"(p));
    return a;
}

// cp.async a [128 x 128B] tile into swizzled smem; 256 threads, 16B each, 4 iters
__device__ __forceinline__ void cpa_tile(uint32_t soff_abs, const char* g,
                                         int stride_bytes, int tid) {
#pragma unroll
    for (int it = 0; it < 4; ++it) {
        int u = it * 256 + tid;
        int r = u >> 3, w = u & 7;
        uint32_t d = soff_abs + SWZ((uint32_t)(r * 128 + w * 16));
        const char* src = g + (size_t)r * stride_bytes + w * 16;
        asm volatile("cp.async.cg.shared.global [%0], [%1], 16;" :: "r"(d), "l"(src));
    }
}
#define CPA_COMMIT() asm volatile("cp.async.commit_group;" ::: "memory")
#define CPA_WAIT(n)  asm volatile("cp.async.wait_group %0;" :: "n"(n) : "memory")

__device__ __forceinline__ void ldmA(uint32_t addr, uint32_t* f) {
    asm volatile("ldmatrix.sync.aligned.m8n8.x4.shared.b16 {%0,%1,%2,%3}, [%4];"
                 : "=r"(f[0]), "=r"(f[1]), "=r"(f[2]), "=r"(f[3]) : "r"(addr));
}
__device__ __forceinline__ void ldmB4(uint32_t addr, uint32_t* f) {
    asm volatile("ldmatrix.sync.aligned.m8n8.x4.shared.b16 {%0,%1,%2,%3}, [%4];"
                 : "=r"(f[0]), "=r"(f[1]), "=r"(f[2]), "=r"(f[3]) : "r"(addr));
}
__device__ __forceinline__ void mma16816(float* c, const uint32_t* a, const uint32_t* b) {
    asm volatile(
        "mma.sync.aligned.m16n8k16.row.col.f32.f16.f16.f32 "
        "{%0,%1,%2,%3}, {%4,%5,%6,%7}, {%8,%9}, {%0,%1,%2,%3};"
        : "+f"(c[0]), "+f"(c[1]), "+f"(c[2]), "+f"(c[3])
        : "r"(a[0]), "r"(a[1]), "r"(a[2]), "r"(a[3]), "r"(b[0]), "r"(b[1]));
}

__device__ __forceinline__ uint32_t b4_addr(uint32_t sB, int ks, int q, int lane, int wn) {
    int grp = lane >> 3;
    int row = wn * 32 + (2 * q + (grp >> 1)) * 8 + (lane & 7);
    uint32_t bo = (uint32_t)(row * 128 + ks * 32 + ((grp & 1) << 4));
    return sB + SWZ(bo);
}

// one 64-wide K chunk; per-warp ks rotation (swizzle on FULL offset)
__device__ __forceinline__ void gemm64(uint32_t sA, uint32_t sB,
                                       float acc[4][4][4], int lane, int wm, int wn,
                                       int rot) {
#pragma unroll
    for (int k2 = 0; k2 < 4; ++k2) {
        int ks = (k2 + rot) & 3;
        uint32_t a[4][4], b[4][2];
#pragma unroll
        for (int mt = 0; mt < 4; ++mt) {
            int row = wm * 64 + mt * 16 + (lane & 15);
            uint32_t bo = (uint32_t)(row * 128 + ks * 32 + ((lane >> 4) << 4));
            ldmA(sA + SWZ(bo), a[mt]);
        }
#pragma unroll
        for (int q = 0; q < 2; ++q)
            ldmB4(b4_addr(sB, ks, q, lane, wn), &b[2 * q][0]);
#pragma unroll
        for (int mt = 0; mt < 4; ++mt)
#pragma unroll
            for (int nt = 0; nt < 4; ++nt)
                mma16816(acc[mt][nt], a[mt], b[nt]);
    }
}

// convert one 64-col slice s of this CTA's 128 rows: fp32 -> fp16 global
__device__ __forceinline__ void conv_slice(const float* __restrict__ xf32,
                                           int row0, int s, int tid) {
    const float4* src = (const float4*)(xf32 + (size_t)row0 * DIN);
    __half* dstbase = g_xh + (size_t)row0 * DIN;
#pragma unroll
    for (int it = 0; it < 8; ++it) {
        int u = it * 256 + tid;          // 0..2047: 128 rows x 16 float4
        int row = u >> 4, seg = u & 15;
        float4 v = src[row * (DIN / 4) + s * 16 + seg];
        __half2 h0 = __floats2half2_rn(v.x, v.y);
        __half2 h1 = __floats2half2_rn(v.z, v.w);
        uint2 pk;
        pk.x = *(uint32_t*)&h0;
        pk.y = *(uint32_t*)&h1;
        *(uint2*)(dstbase + (size_t)row * DIN + s * 64 + seg * 4) = pk;
    }
}

// ---------------- prep kernel (weights only) ----------------
__global__ void prep_w(const float* __restrict__ W1, const float* __restrict__ W2) {
    int i = blockIdx.x * 256 + threadIdx.x;
    const int n1 = N_C * DIN * HID;
    if (i < n1) {
        int c = i / (DIN * HID);
        int rem = i % (DIN * HID);
        int h = rem / DIN;
        int d = rem % DIN;
        g_w1t[i] = __float2half_rn(W1[(c * DIN + d) * HID + h]);
    } else {
        int k = i - n1;
        if (k < N_C * HID * HID) {
            int c = k / (HID * HID);
            int rem = k % (HID * HID);
            int ho = rem / HID;
            int hi = rem % HID;
            g_w2t[k] = __float2half_rn(W2[(c * HID + hi) * HID + ho]);
        }
    }
}

// ---------------- main fused MLP kernel ----------------
__global__ void __launch_bounds__(256, 2) mlp_main(
    const float* __restrict__ xf32,
    const float* __restrict__ b1, const float* __restrict__ b2,
    const float* __restrict__ W3, const float* __restrict__ b3,
    float* __restrict__ out) {
    extern __shared__ char smem[];
    const uint32_t sbase = smem_u32(smem);
    const int tid  = threadIdx.x;
    const int lane = tid & 31;
    const int wid  = tid >> 5;
    const int wm   = wid >> 2;
    const int wn   = wid & 3;
    const int rot  = wid & 3;
    const int row0 = blockIdx.x * TILE_M;

    float* b1s    = (float*)(smem + OFF_B1S);
    float* b2s    = (float*)(smem + OFF_B2S);
    float* w3s    = (float*)(smem + OFF_W3S);
    float* rowacc = (float*)(smem + OFF_ACC);

    float acc[4][4][4];
    const char* xg = (const char*)(g_xh + (size_t)row0 * DIN);

    // prologue: convert slices 0..2 only (rest woven JIT into channel-0 loop)
    conv_slice(xf32, row0, 0, tid);
    conv_slice(xf32, row0, 1, tid);
    conv_slice(xf32, row0, 2, tid);
    __syncthreads();   // converts visible CTA-wide before cp.async reads

    // issue channel-0 chunk 0
    cpa_tile(sbase + OFF_SA(0), xg, DIN * 2, tid);
    cpa_tile(sbase + OFF_SB(0), (const char*)g_w1t, DIN * 2, tid);
    CPA_COMMIT();

#pragma unroll 1
    for (int c = 0; c < N_C; ++c) {
        if (tid < HID) {
            b1s[tid] = b1[c * HID + tid];
            b2s[tid] = b2[c * HID + tid];
            w3s[tid] = W3[c * HID + tid];
            rowacc[tid] = 0.f;
        }
#pragma unroll
        for (int mt = 0; mt < 4; ++mt)
#pragma unroll
            for (int nt = 0; nt < 4; ++nt)
#pragma unroll
                for (int i = 0; i < 4; ++i) acc[mt][nt][i] = 0.f;

        const char* w1c = (const char*)(g_w1t + (size_t)c * HID * DIN);

        // ==== GEMM1: 2-stage, round-2 ordering; channel 0 weaves x conversion ====
        // invariant: chunk j+1's x-slice (j+1) was converted at iter j-2 (or prologue)
        // and made visible by that iter's trailing __syncthreads.
#pragma unroll 1
        for (int j = 0; j < NCHUNK; ++j) {
            if (j < NCHUNK - 1) {
                int nb = (j + 1) & 1;
                cpa_tile(sbase + OFF_SA(nb), xg + (size_t)(j + 1) * KC * 2, DIN * 2, tid);
                cpa_tile(sbase + OFF_SB(nb), w1c + (size_t)(j + 1) * KC * 2, DIN * 2, tid);
                CPA_COMMIT();
                CPA_WAIT(1);
            } else {
                CPA_WAIT(0);
            }
            __syncthreads();
            gemm64(sbase + OFF_SA(j & 1), sbase + OFF_SB(j & 1), acc, lane, wm, wn, rot);
            if (c == 0 && j + 3 < NCHUNK) conv_slice(xf32, row0, j + 3, tid);
            __syncthreads();
        }

        // issue W2 (both chunks) into B slots — overlaps epilogue-1 STS
        {
            const char* w2c = (const char*)(g_w2t + (size_t)c * HID * HID);
            cpa_tile(sbase + OFF_SB(0), w2c, HID * 2, tid);
            cpa_tile(sbase + OFF_SB(1), w2c + (size_t)KC * 2, HID * 2, tid);
            CPA_COMMIT();
        }

        // ==== epilogue 1: relu(acc + b1) -> fp16 h1 (own region) ====
#pragma unroll
        for (int mt = 0; mt < 4; ++mt) {
            int r1 = wm * 64 + mt * 16 + (lane >> 2);
#pragma unroll
            for (int nt = 0; nt < 4; ++nt) {
                int n = wn * 32 + nt * 8 + (lane & 3) * 2;
                uint32_t chb = OFF_H1 + (uint32_t)(n >> 6) * 16384u;
                uint32_t nc = (uint32_t)(n & 63);
                float* cc = acc[mt][nt];
                __half2 h0 = __floats2half2_rn(fmaxf(cc[0] + b1s[n], 0.f),
                                               fmaxf(cc[1] + b1s[n + 1], 0.f));
                __half2 h1v = __floats2half2_rn(fmaxf(cc[2] + b1s[n], 0.f),
                                                fmaxf(cc[3] + b1s[n + 1], 0.f));
                *(__half2*)(smem + chb + SWZ((uint32_t)r1 * 128u + nc * 2u)) = h0;
                *(__half2*)(smem + chb + SWZ((uint32_t)(r1 + 8) * 128u + nc * 2u)) = h1v;
            }
        }
        CPA_WAIT(0);
        __syncthreads();   // h1 + W2 ready

        // ==== GEMM2: h1[128,128] @ W2^T ====
#pragma unroll
        for (int mt = 0; mt < 4; ++mt)
#pragma unroll
            for (int nt = 0; nt < 4; ++nt)
#pragma unroll
                for (int i = 0; i < 4; ++i) acc[mt][nt][i] = 0.f;

        gemm64(sbase + OFF_H1,          sbase + OFF_SB(0), acc, lane, wm, wn, rot);
        gemm64(sbase + OFF_H1 + 16384u, sbase + OFF_SB(1), acc, lane, wm, wn, rot);
        __syncthreads();   // slots free

        // prefetch next channel chunk 0 — overlaps epilogue-2 math
        if (c < N_C - 1) {
            const char* w1n = (const char*)(g_w1t + (size_t)(c + 1) * HID * DIN);
            cpa_tile(sbase + OFF_SA(0), xg, DIN * 2, tid);
            cpa_tile(sbase + OFF_SB(0), w1n, DIN * 2, tid);
            CPA_COMMIT();
        }

        // ==== epilogue 2: out = relu(acc + b2) . W3 + b3 ====
#pragma unroll
        for (int mt = 0; mt < 4; ++mt) {
            float p1 = 0.f, p2 = 0.f;
#pragma unroll
            for (int nt = 0; nt < 4; ++nt) {
                int n = wn * 32 + nt * 8 + (lane & 3) * 2;
                float* cc = acc[mt][nt];
                float w0 = w3s[n], w1v = w3s[n + 1];
                float c2a = b2s[n], c2b = b2s[n + 1];
                p1 += fmaxf(cc[0] + c2a, 0.f) * w0 + fmaxf(cc[1] + c2b, 0.f) * w1v;
                p2 += fmaxf(cc[2] + c2a, 0.f) * w0 + fmaxf(cc[3] + c2b, 0.f) * w1v;
            }
            p1 += __shfl_xor_sync(0xFFFFFFFFu, p1, 1);
            p1 += __shfl_xor_sync(0xFFFFFFFFu, p1, 2);
            p2 += __shfl_xor_sync(0xFFFFFFFFu, p2, 1);
            p2 += __shfl_xor_sync(0xFFFFFFFFu, p2, 2);
            if ((lane & 3) == 0) {
                int r = wm * 64 + mt * 16 + (lane >> 2);
                atomicAdd(&rowacc[r], p1);
                atomicAdd(&rowacc[r + 8], p2);
            }
        }
        __syncthreads();
        if (tid < TILE_M)
            out[(size_t)(row0 + tid) * N_C + c] = rowacc[tid] + b3[c];
        __syncthreads();   // protect smem vectors before next channel rewrites
    }
}

// ---------------- launch ----------------
extern "C" void kernel_launch(void* const* d_in, const int* in_sizes, int n_in,
                              void* d_out, int out_size) {
    const float* x  = (const float*)d_in[0];
    const float* W1 = (const float*)d_in[1];
    const float* b1 = (const float*)d_in[2];
    const float* W2 = (const float*)d_in[3];
    const float* b2 = (const float*)d_in[4];
    const float* W3 = (const float*)d_in[5];
    const float* b3 = (const float*)d_in[6];
    float* out = (float*)d_out;

    const int npts = in_sizes[0] / DIN;               // 65536
    const int wtot = N_C * DIN * HID + N_C * HID * HID;
    prep_w<<<(wtot + 255) / 256, 256>>>(W1, W2);

    cudaFuncSetAttribute(mlp_main, cudaFuncAttributeMaxDynamicSharedMemorySize, SMEM_TOTAL);
    mlp_main<<<npts / TILE_M, 256, SMEM_TOTAL>>>(x, b1, b2, W3, b3, out);
}

// round 11
// speedup vs baseline: 1.0580x; 1.0498x over previous
#include <cuda_runtime.h>
#include <cuda_fp16.h>
#include <cstdint>

#define N_C    16
#define DIN    1024
#define HID    128
#define TILE_M 128
#define KC     64
#define NCHUNK (DIN / KC)   // 16

// ---------------- device scratch ----------------
__device__ __align__(1024) __half g_xh [67108864];        // 65536*1024 fp16
__device__ __align__(1024) __half g_w1t[N_C * HID * DIN]; // [c][h][d] K-major
__device__ __align__(1024) __half g_w2t[N_C * HID * HID]; // [c][ho][hi] K-major

// ---------------- smem layout ----------------
#define OFF_SA(s)  ((uint32_t)(s) * 16384u)            // 0, 16384
#define OFF_SB(s)  (32768u + (uint32_t)(s) * 16384u)   // 32768, 49152
#define OFF_H1     65536u                              // 32KB: chunk0 @+0, chunk1 @+16384
#define OFF_B1S    98304u
#define OFF_B2S    98816u
#define OFF_W3S    99328u
#define OFF_ACC    99840u
#define SMEM_TOTAL 100352u

#define SWZ(bo) ((bo) ^ (((bo) >> 3) & 0x70))

__device__ __forceinline__ uint32_t smem_u32(const void* p) {
    uint32_t a;
    asm("{ .reg .u64 t; cvta.to.shared.u64 t, %1; cvt.u32.u64 %0, t; }" : "=r"(a) : "l"(p));
    return a;
}

// cp.async a [128 x 128B] tile into swizzled smem; 256 threads, 16B each, 4 iters
__device__ __forceinline__ void cpa_tile(uint32_t soff_abs, const char* g,
                                         int stride_bytes, int tid) {
#pragma unroll
    for (int it = 0; it < 4; ++it) {
        int u = it * 256 + tid;
        int r = u >> 3, w = u & 7;
        uint32_t d = soff_abs + SWZ((uint32_t)(r * 128 + w * 16));
        const char* src = g + (size_t)r * stride_bytes + w * 16;
        asm volatile("cp.async.cg.shared.global [%0], [%1], 16;" :: "r"(d), "l"(src));
    }
}
#define CPA_COMMIT() asm volatile("cp.async.commit_group;" ::: "memory")
#define CPA_WAIT(n)  asm volatile("cp.async.wait_group %0;" :: "n"(n) : "memory")

__device__ __forceinline__ void ldmA(uint32_t addr, uint32_t* f) {
    asm volatile("ldmatrix.sync.aligned.m8n8.x4.shared.b16 {%0,%1,%2,%3}, [%4];"
                 : "=r"(f[0]), "=r"(f[1]), "=r"(f[2]), "=r"(f[3]) : "r"(addr));
}
__device__ __forceinline__ void ldmB4(uint32_t addr, uint32_t* f) {
    asm volatile("ldmatrix.sync.aligned.m8n8.x4.shared.b16 {%0,%1,%2,%3}, [%4];"
                 : "=r"(f[0]), "=r"(f[1]), "=r"(f[2]), "=r"(f[3]) : "r"(addr));
}
__device__ __forceinline__ void mma16816(float* c, const uint32_t* a, const uint32_t* b) {
    asm volatile(
        "mma.sync.aligned.m16n8k16.row.col.f32.f16.f16.f32 "
        "{%0,%1,%2,%3}, {%4,%5,%6,%7}, {%8,%9}, {%0,%1,%2,%3};"
        : "+f"(c[0]), "+f"(c[1]), "+f"(c[2]), "+f"(c[3])
        : "r"(a[0]), "r"(a[1]), "r"(a[2]), "r"(a[3]), "r"(b[0]), "r"(b[1]));
}

__device__ __forceinline__ uint32_t b4_addr(uint32_t sB, int ks, int q, int lane, int wn) {
    int grp = lane >> 3;
    int row = wn * 32 + (2 * q + (grp >> 1)) * 8 + (lane & 7);
    uint32_t bo = (uint32_t)(row * 128 + ks * 32 + ((grp & 1) << 4));
    return sB + SWZ(bo);
}

// one 64-wide K chunk: A [128x64] at sA, B [128x64] at sB (natural ks order)
__device__ __forceinline__ void gemm64(uint32_t sA, uint32_t sB,
                                       float acc[4][4][4], int lane, int wm, int wn) {
#pragma unroll
    for (int ks = 0; ks < 4; ++ks) {
        uint32_t a[4][4], b[4][2];
#pragma unroll
        for (int mt = 0; mt < 4; ++mt) {
            int row = wm * 64 + mt * 16 + (lane & 15);
            uint32_t bo = (uint32_t)(row * 128 + ks * 32 + ((lane >> 4) << 4));
            ldmA(sA + SWZ(bo), a[mt]);
        }
#pragma unroll
        for (int q = 0; q < 2; ++q)
            ldmB4(b4_addr(sB, ks, q, lane, wn), &b[2 * q][0]);
#pragma unroll
        for (int mt = 0; mt < 4; ++mt)
#pragma unroll
            for (int nt = 0; nt < 4; ++nt)
                mma16816(acc[mt][nt], a[mt], b[nt]);
    }
}

// ---------------- prep kernel (weights only) ----------------
__global__ void prep_w(const float* __restrict__ W1, const float* __restrict__ W2) {
    int i = blockIdx.x * 256 + threadIdx.x;
    const int n1 = N_C * DIN * HID;
    if (i < n1) {
        int c = i / (DIN * HID);
        int rem = i % (DIN * HID);
        int h = rem / DIN;
        int d = rem % DIN;
        g_w1t[i] = __float2half_rn(W1[(c * DIN + d) * HID + h]);
    } else {
        int k = i - n1;
        if (k < N_C * HID * HID) {
            int c = k / (HID * HID);
            int rem = k % (HID * HID);
            int ho = rem / HID;
            int hi = rem % HID;
            g_w2t[k] = __float2half_rn(W2[(c * HID + hi) * HID + ho]);
        }
    }
}

// ---------------- main fused MLP kernel ----------------
__global__ void __launch_bounds__(256, 2) mlp_main(
    const float* __restrict__ xf32,
    const float* __restrict__ b1, const float* __restrict__ b2,
    const float* __restrict__ W3, const float* __restrict__ b3,
    float* __restrict__ out) {
    extern __shared__ char smem[];
    const uint32_t sbase = smem_u32(smem);
    const int tid  = threadIdx.x;
    const int lane = tid & 31;
    const int wid  = tid >> 5;
    const int wm   = wid >> 2;
    const int wn   = wid & 3;
    const int row0 = blockIdx.x * TILE_M;

    float* b1s    = (float*)(smem + OFF_B1S);
    float* b2s    = (float*)(smem + OFF_B2S);
    float* w3s    = (float*)(smem + OFF_W3S);
    float* rowacc = (float*)(smem + OFF_ACC);

    // ---- x -> fp16 conversion (this CTA's 128 rows), MLP-8 batched ----
    {
        const float4* xs = (const float4*)(xf32 + (size_t)row0 * DIN);
        uint2* o = (uint2*)(g_xh + (size_t)row0 * DIN);
        // 128 float4 per thread total; batches of 8 in-flight loads
#pragma unroll 1
        for (int base = 0; base < 128; base += 8) {
            float4 v[8];
#pragma unroll
            for (int k = 0; k < 8; ++k)
                v[k] = xs[(base + k) * 256 + tid];
#pragma unroll
            for (int k = 0; k < 8; ++k) {
                __half2 h0 = __floats2half2_rn(v[k].x, v[k].y);
                __half2 h1 = __floats2half2_rn(v[k].z, v[k].w);
                uint2 pk;
                pk.x = *(uint32_t*)&h0;
                pk.y = *(uint32_t*)&h1;
                o[(base + k) * 256 + tid] = pk;
            }
        }
        __syncthreads();   // CTA-scope: global writes visible before cp.async reads
    }

    float acc[4][4][4];
    const char* xg = (const char*)(g_xh + (size_t)row0 * DIN);

    // prologue: channel 0 chunk 0
    {
        cpa_tile(sbase + OFF_SA(0), xg, DIN * 2, tid);
        cpa_tile(sbase + OFF_SB(0), (const char*)g_w1t, DIN * 2, tid);
        CPA_COMMIT();
    }

#pragma unroll 1
    for (int c = 0; c < N_C; ++c) {
        if (tid < HID) {
            b1s[tid] = b1[c * HID + tid];
            b2s[tid] = b2[c * HID + tid];
            w3s[tid] = W3[c * HID + tid];
            rowacc[tid] = 0.f;
        }
#pragma unroll
        for (int mt = 0; mt < 4; ++mt)
#pragma unroll
            for (int nt = 0; nt < 4; ++nt)
#pragma unroll
                for (int i = 0; i < 4; ++i) acc[mt][nt][i] = 0.f;

        const char* w1c = (const char*)(g_w1t + (size_t)c * HID * DIN);

        // ==== GEMM1: round-2 ordering (issue j+1 -> wait -> sync -> gemm -> sync) ====
#pragma unroll 1
        for (int j = 0; j < NCHUNK; ++j) {
            if (j < NCHUNK - 1) {
                int nb = (j + 1) & 1;
                cpa_tile(sbase + OFF_SA(nb), xg + (size_t)(j + 1) * KC * 2, DIN * 2, tid);
                cpa_tile(sbase + OFF_SB(nb), w1c + (size_t)(j + 1) * KC * 2, DIN * 2, tid);
                CPA_COMMIT();
                CPA_WAIT(1);
            } else {
                CPA_WAIT(0);
            }
            __syncthreads();
            gemm64(sbase + OFF_SA(j & 1), sbase + OFF_SB(j & 1), acc, lane, wm, wn);
            __syncthreads();
        }

        // issue W2 (both chunks) into B slots — overlaps epilogue-1 STS
        {
            const char* w2c = (const char*)(g_w2t + (size_t)c * HID * HID);
            cpa_tile(sbase + OFF_SB(0), w2c, HID * 2, tid);
            cpa_tile(sbase + OFF_SB(1), w2c + (size_t)KC * 2, HID * 2, tid);
            CPA_COMMIT();
        }

        // ==== epilogue 1: relu(acc + b1) -> fp16 h1 (own region) ====
#pragma unroll
        for (int mt = 0; mt < 4; ++mt) {
            int r1 = wm * 64 + mt * 16 + (lane >> 2);
#pragma unroll
            for (int nt = 0; nt < 4; ++nt) {
                int n = wn * 32 + nt * 8 + (lane & 3) * 2;
                uint32_t chb = OFF_H1 + (uint32_t)(n >> 6) * 16384u;
                uint32_t nc = (uint32_t)(n & 63);
                float* cc = acc[mt][nt];
                __half2 h0 = __floats2half2_rn(fmaxf(cc[0] + b1s[n], 0.f),
                                               fmaxf(cc[1] + b1s[n + 1], 0.f));
                __half2 h1v = __floats2half2_rn(fmaxf(cc[2] + b1s[n], 0.f),
                                                fmaxf(cc[3] + b1s[n + 1], 0.f));
                *(__half2*)(smem + chb + SWZ((uint32_t)r1 * 128u + nc * 2u)) = h0;
                *(__half2*)(smem + chb + SWZ((uint32_t)(r1 + 8) * 128u + nc * 2u)) = h1v;
            }
        }
        CPA_WAIT(0);
        __syncthreads();   // h1 + W2 ready

        // ==== GEMM2: h1[128,128] @ W2^T ====
#pragma unroll
        for (int mt = 0; mt < 4; ++mt)
#pragma unroll
            for (int nt = 0; nt < 4; ++nt)
#pragma unroll
                for (int i = 0; i < 4; ++i) acc[mt][nt][i] = 0.f;

        gemm64(sbase + OFF_H1,          sbase + OFF_SB(0), acc, lane, wm, wn);
        gemm64(sbase + OFF_H1 + 16384u, sbase + OFF_SB(1), acc, lane, wm, wn);
        __syncthreads();   // slots free

        // prefetch next channel chunk 0 — overlaps epilogue-2 math
        if (c < N_C - 1) {
            const char* w1n = (const char*)(g_w1t + (size_t)(c + 1) * HID * DIN);
            cpa_tile(sbase + OFF_SA(0), xg, DIN * 2, tid);
            cpa_tile(sbase + OFF_SB(0), w1n, DIN * 2, tid);
            CPA_COMMIT();
        }

        // ==== epilogue 2: out = relu(acc + b2) . W3 + b3 ====
#pragma unroll
        for (int mt = 0; mt < 4; ++mt) {
            float p1 = 0.f, p2 = 0.f;
#pragma unroll
            for (int nt = 0; nt < 4; ++nt) {
                int n = wn * 32 + nt * 8 + (lane & 3) * 2;
                float* cc = acc[mt][nt];
                float w0 = w3s[n], w1v = w3s[n + 1];
                float c2a = b2s[n], c2b = b2s[n + 1];
                p1 += fmaxf(cc[0] + c2a, 0.f) * w0 + fmaxf(cc[1] + c2b, 0.f) * w1v;
                p2 += fmaxf(cc[2] + c2a, 0.f) * w0 + fmaxf(cc[3] + c2b, 0.f) * w1v;
            }
            p1 += __shfl_xor_sync(0xFFFFFFFFu, p1, 1);
            p1 += __shfl_xor_sync(0xFFFFFFFFu, p1, 2);
            p2 += __shfl_xor_sync(0xFFFFFFFFu, p2, 1);
            p2 += __shfl_xor_sync(0xFFFFFFFFu, p2, 2);
            if ((lane & 3) == 0) {
                int r = wm * 64 + mt * 16 + (lane >> 2);
                atomicAdd(&rowacc[r], p1);
                atomicAdd(&rowacc[r + 8], p2);
            }
        }
        __syncthreads();
        if (tid < TILE_M)
            out[(size_t)(row0 + tid) * N_C + c] = rowacc[tid] + b3[c];
        __syncthreads();   // protect smem vectors before next channel rewrites
    }
}

// ---------------- launch ----------------
extern "C" void kernel_launch(void* const* d_in, const int* in_sizes, int n_in,
                              void* d_out, int out_size) {
    const float* x  = (const float*)d_in[0];
    const float* W1 = (const float*)d_in[1];
    const float* b1 = (const float*)d_in[2];
    const float* W2 = (const float*)d_in[3];
    const float* b2 = (const float*)d_in[4];
    const float* W3 = (const float*)d_in[5];
    const float* b3 = (const float*)d_in[6];
    float* out = (float*)d_out;

    const int npts = in_sizes[0] / DIN;               // 65536
    const int wtot = N_C * DIN * HID + N_C * HID * HID;
    prep_w<<<(wtot + 255) / 256, 256>>>(W1, W2);

    cudaFuncSetAttribute(mlp_main, cudaFuncAttributeMaxDynamicSharedMemorySize, SMEM_TOTAL);
    mlp_main<<<npts / TILE_M, 256, SMEM_TOTAL>>>(x, b1, b2, W3, b3, out);
}

// round 12
// speedup vs baseline: 1.2005x; 1.1347x over previous
#include <cuda_runtime.h>
#include <cuda_fp16.h>
#include <cstdint>

#define N_C    16
#define DIN    1024
#define HID    128
#define TILE_M 128
#define KC     64
#define NCHUNK (DIN / KC)   // 16
#define CH_PER_CTA 4

// ---------------- device scratch ----------------
__device__ __align__(1024) __half g_xh [67108864];        // 65536*1024 fp16
__device__ __align__(1024) __half g_w1t[N_C * HID * DIN]; // [c][h][d] K-major
__device__ __align__(1024) __half g_w2t[N_C * HID * HID]; // [c][ho][hi] K-major

// ---------------- smem layout ----------------
#define OFF_SA(s)  ((uint32_t)(s) * 16384u)            // 0, 16384
#define OFF_SB(s)  (32768u + (uint32_t)(s) * 16384u)   // 32768, 49152
#define OFF_H1     65536u                              // 32KB: chunk0 @+0, chunk1 @+16384
#define OFF_B1S    98304u
#define OFF_B2S    98816u
#define OFF_W3S    99328u
#define OFF_ACC    99840u
#define SMEM_TOTAL 100352u

#define SWZ(bo) ((bo) ^ (((bo) >> 3) & 0x70))

__device__ __forceinline__ uint32_t smem_u32(const void* p) {
    uint32_t a;
    asm("{ .reg .u64 t; cvta.to.shared.u64 t, %1; cvt.u32.u64 %0, t; }" : "=r"(a) : "l"(p));
    return a;
}

// cp.async a [128 x 128B] tile into swizzled smem; 256 threads, 16B each, 4 iters
__device__ __forceinline__ void cpa_tile(uint32_t soff_abs, const char* g,
                                         int stride_bytes, int tid) {
#pragma unroll
    for (int it = 0; it < 4; ++it) {
        int u = it * 256 + tid;
        int r = u >> 3, w = u & 7;
        uint32_t d = soff_abs + SWZ((uint32_t)(r * 128 + w * 16));
        const char* src = g + (size_t)r * stride_bytes + w * 16;
        asm volatile("cp.async.cg.shared.global [%0], [%1], 16;" :: "r"(d), "l"(src));
    }
}
#define CPA_COMMIT() asm volatile("cp.async.commit_group;" ::: "memory")
#define CPA_WAIT(n)  asm volatile("cp.async.wait_group %0;" :: "n"(n) : "memory")

__device__ __forceinline__ void ldmA(uint32_t addr, uint32_t* f) {
    asm volatile("ldmatrix.sync.aligned.m8n8.x4.shared.b16 {%0,%1,%2,%3}, [%4];"
                 : "=r"(f[0]), "=r"(f[1]), "=r"(f[2]), "=r"(f[3]) : "r"(addr));
}
__device__ __forceinline__ void ldmB4(uint32_t addr, uint32_t* f) {
    asm volatile("ldmatrix.sync.aligned.m8n8.x4.shared.b16 {%0,%1,%2,%3}, [%4];"
                 : "=r"(f[0]), "=r"(f[1]), "=r"(f[2]), "=r"(f[3]) : "r"(addr));
}
__device__ __forceinline__ void mma16816(float* c, const uint32_t* a, const uint32_t* b) {
    asm volatile(
        "mma.sync.aligned.m16n8k16.row.col.f32.f16.f16.f32 "
        "{%0,%1,%2,%3}, {%4,%5,%6,%7}, {%8,%9}, {%0,%1,%2,%3};"
        : "+f"(c[0]), "+f"(c[1]), "+f"(c[2]), "+f"(c[3])
        : "r"(a[0]), "r"(a[1]), "r"(a[2]), "r"(a[3]), "r"(b[0]), "r"(b[1]));
}

__device__ __forceinline__ uint32_t b4_addr(uint32_t sB, int ks, int q, int lane, int wn) {
    int grp = lane >> 3;
    int row = wn * 32 + (2 * q + (grp >> 1)) * 8 + (lane & 7);
    uint32_t bo = (uint32_t)(row * 128 + ks * 32 + ((grp & 1) << 4));
    return sB + SWZ(bo);
}

// one 64-wide K chunk: A [128x64] at sA, B [128x64] at sB
__device__ __forceinline__ void gemm64(uint32_t sA, uint32_t sB,
                                       float acc[4][4][4], int lane, int wm, int wn) {
#pragma unroll
    for (int ks = 0; ks < 4; ++ks) {
        uint32_t a[4][4], b[4][2];
#pragma unroll
        for (int mt = 0; mt < 4; ++mt) {
            int row = wm * 64 + mt * 16 + (lane & 15);
            uint32_t bo = (uint32_t)(row * 128 + ks * 32 + ((lane >> 4) << 4));
            ldmA(sA + SWZ(bo), a[mt]);
        }
#pragma unroll
        for (int q = 0; q < 2; ++q)
            ldmB4(b4_addr(sB, ks, q, lane, wn), &b[2 * q][0]);
#pragma unroll
        for (int mt = 0; mt < 4; ++mt)
#pragma unroll
            for (int nt = 0; nt < 4; ++nt)
                mma16816(acc[mt][nt], a[mt], b[nt]);
    }
}

// ---------------- merged prep kernel: x -> fp16 + W transposes ----------------
__global__ void prep_all(const float* __restrict__ x, const float* __restrict__ W1,
                         const float* __restrict__ W2, int xblocks) {
    if ((int)blockIdx.x < xblocks) {
        int i = blockIdx.x * 256 + threadIdx.x;
        float4 v = ((const float4*)x)[i];
        __half2* o = (__half2*)g_xh;
        o[2 * i]     = __floats2half2_rn(v.x, v.y);
        o[2 * i + 1] = __floats2half2_rn(v.z, v.w);
    } else {
        int i = (blockIdx.x - xblocks) * 256 + threadIdx.x;
        const int n1 = N_C * DIN * HID;
        if (i < n1) {
            int c = i / (DIN * HID);
            int rem = i % (DIN * HID);
            int h = rem / DIN;
            int d = rem % DIN;
            g_w1t[i] = __float2half_rn(W1[(c * DIN + d) * HID + h]);
        } else {
            int k = i - n1;
            if (k < N_C * HID * HID) {
                int c = k / (HID * HID);
                int rem = k % (HID * HID);
                int ho = rem / HID;
                int hi = rem % HID;
                g_w2t[k] = __float2half_rn(W2[(c * HID + hi) * HID + ho]);
            }
        }
    }
}

// ---------------- main fused MLP kernel (4 channels per CTA) ----------------
__global__ void __launch_bounds__(256, 2) mlp_main(
    const float* __restrict__ b1, const float* __restrict__ b2,
    const float* __restrict__ W3, const float* __restrict__ b3,
    float* __restrict__ out) {
    extern __shared__ char smem[];
    const uint32_t sbase = smem_u32(smem);
    const int tid  = threadIdx.x;
    const int lane = tid & 31;
    const int wid  = tid >> 5;
    const int wm   = wid >> 2;
    const int wn   = wid & 3;
    // consecutive blockIdx -> same tile, different channel group (L2 co-residency)
    const int row0 = (blockIdx.x >> 2) * TILE_M;
    const int c0   = (blockIdx.x & 3) * CH_PER_CTA;

    float* b1s    = (float*)(smem + OFF_B1S);
    float* b2s    = (float*)(smem + OFF_B2S);
    float* w3s    = (float*)(smem + OFF_W3S);
    float* rowacc = (float*)(smem + OFF_ACC);

    float acc[4][4][4];
    const char* xg = (const char*)(g_xh + (size_t)row0 * DIN);

    // prologue: first channel chunk 0
    {
        const char* w1c = (const char*)(g_w1t + (size_t)c0 * HID * DIN);
        cpa_tile(sbase + OFF_SA(0), xg, DIN * 2, tid);
        cpa_tile(sbase + OFF_SB(0), w1c, DIN * 2, tid);
        CPA_COMMIT();
    }

#pragma unroll 1
    for (int cc = 0; cc < CH_PER_CTA; ++cc) {
        const int c = c0 + cc;
        if (tid < HID) {
            b1s[tid] = b1[c * HID + tid];
            b2s[tid] = b2[c * HID + tid];
            w3s[tid] = W3[c * HID + tid];
            rowacc[tid] = 0.f;
        }
#pragma unroll
        for (int mt = 0; mt < 4; ++mt)
#pragma unroll
            for (int nt = 0; nt < 4; ++nt)
#pragma unroll
                for (int i = 0; i < 4; ++i) acc[mt][nt][i] = 0.f;

        const char* w1c = (const char*)(g_w1t + (size_t)c * HID * DIN);

        // ==== GEMM1: round-2 ordering (issue j+1 -> wait -> sync -> gemm -> sync) ====
#pragma unroll 1
        for (int j = 0; j < NCHUNK; ++j) {
            if (j < NCHUNK - 1) {
                int nb = (j + 1) & 1;
                cpa_tile(sbase + OFF_SA(nb), xg + (size_t)(j + 1) * KC * 2, DIN * 2, tid);
                cpa_tile(sbase + OFF_SB(nb), w1c + (size_t)(j + 1) * KC * 2, DIN * 2, tid);
                CPA_COMMIT();
                CPA_WAIT(1);
            } else {
                CPA_WAIT(0);
            }
            __syncthreads();
            gemm64(sbase + OFF_SA(j & 1), sbase + OFF_SB(j & 1), acc, lane, wm, wn);
            __syncthreads();
        }

        // issue W2 (both chunks) into B slots — overlaps epilogue-1 STS
        {
            const char* w2c = (const char*)(g_w2t + (size_t)c * HID * HID);
            cpa_tile(sbase + OFF_SB(0), w2c, HID * 2, tid);
            cpa_tile(sbase + OFF_SB(1), w2c + (size_t)KC * 2, HID * 2, tid);
            CPA_COMMIT();
        }

        // ==== epilogue 1: relu(acc + b1) -> fp16 h1 (own region) ====
#pragma unroll
        for (int mt = 0; mt < 4; ++mt) {
            int r1 = wm * 64 + mt * 16 + (lane >> 2);
#pragma unroll
            for (int nt = 0; nt < 4; ++nt) {
                int n = wn * 32 + nt * 8 + (lane & 3) * 2;
                uint32_t chb = OFF_H1 + (uint32_t)(n >> 6) * 16384u;
                uint32_t nc = (uint32_t)(n & 63);
                float* cc2 = acc[mt][nt];
                __half2 h0 = __floats2half2_rn(fmaxf(cc2[0] + b1s[n], 0.f),
                                               fmaxf(cc2[1] + b1s[n + 1], 0.f));
                __half2 h1v = __floats2half2_rn(fmaxf(cc2[2] + b1s[n], 0.f),
                                                fmaxf(cc2[3] + b1s[n + 1], 0.f));
                *(__half2*)(smem + chb + SWZ((uint32_t)r1 * 128u + nc * 2u)) = h0;
                *(__half2*)(smem + chb + SWZ((uint32_t)(r1 + 8) * 128u + nc * 2u)) = h1v;
            }
        }
        CPA_WAIT(0);
        __syncthreads();   // h1 + W2 ready

        // ==== GEMM2: h1[128,128] @ W2^T ====
#pragma unroll
        for (int mt = 0; mt < 4; ++mt)
#pragma unroll
            for (int nt = 0; nt < 4; ++nt)
#pragma unroll
                for (int i = 0; i < 4; ++i) acc[mt][nt][i] = 0.f;

        gemm64(sbase + OFF_H1,          sbase + OFF_SB(0), acc, lane, wm, wn);
        gemm64(sbase + OFF_H1 + 16384u, sbase + OFF_SB(1), acc, lane, wm, wn);
        __syncthreads();   // slots free

        // prefetch next channel chunk 0 — overlaps epilogue-2 math
        if (cc < CH_PER_CTA - 1) {
            const char* w1n = (const char*)(g_w1t + (size_t)(c + 1) * HID * DIN);
            cpa_tile(sbase + OFF_SA(0), xg, DIN * 2, tid);
            cpa_tile(sbase + OFF_SB(0), w1n, DIN * 2, tid);
            CPA_COMMIT();
        }

        // ==== epilogue 2: out = relu(acc + b2) . W3 + b3 ====
#pragma unroll
        for (int mt = 0; mt < 4; ++mt) {
            float p1 = 0.f, p2 = 0.f;
#pragma unroll
            for (int nt = 0; nt < 4; ++nt) {
                int n = wn * 32 + nt * 8 + (lane & 3) * 2;
                float* cc2 = acc[mt][nt];
                float w0 = w3s[n], w1v = w3s[n + 1];
                float c2a = b2s[n], c2b = b2s[n + 1];
                p1 += fmaxf(cc2[0] + c2a, 0.f) * w0 + fmaxf(cc2[1] + c2b, 0.f) * w1v;
                p2 += fmaxf(cc2[2] + c2a, 0.f) * w0 + fmaxf(cc2[3] + c2b, 0.f) * w1v;
            }
            p1 += __shfl_xor_sync(0xFFFFFFFFu, p1, 1);
            p1 += __shfl_xor_sync(0xFFFFFFFFu, p1, 2);
            p2 += __shfl_xor_sync(0xFFFFFFFFu, p2, 1);
            p2 += __shfl_xor_sync(0xFFFFFFFFu, p2, 2);
            if ((lane & 3) == 0) {
                int r = wm * 64 + mt * 16 + (lane >> 2);
                atomicAdd(&rowacc[r], p1);
                atomicAdd(&rowacc[r + 8], p2);
            }
        }
        __syncthreads();
        if (tid < TILE_M)
            out[(size_t)(row0 + tid) * N_C + c] = rowacc[tid] + b3[c];
        __syncthreads();   // protect smem vectors before next channel rewrites
    }
}

// ---------------- launch ----------------
extern "C" void kernel_launch(void* const* d_in, const int* in_sizes, int n_in,
                              void* d_out, int out_size) {
    const float* x  = (const float*)d_in[0];
    const float* W1 = (const float*)d_in[1];
    const float* b1 = (const float*)d_in[2];
    const float* W2 = (const float*)d_in[3];
    const float* b2 = (const float*)d_in[4];
    const float* W3 = (const float*)d_in[5];
    const float* b3 = (const float*)d_in[6];
    float* out = (float*)d_out;

    const int npts = in_sizes[0] / DIN;               // 65536
    const int xblocks = npts * (DIN / 4) / 256;       // 65536
    const int wtot = N_C * DIN * HID + N_C * HID * HID;
    const int wblocks = (wtot + 255) / 256;

    prep_all<<<xblocks + wblocks, 256>>>(x, W1, W2, xblocks);

    cudaFuncSetAttribute(mlp_main, cudaFuncAttributeMaxDynamicSharedMemorySize, SMEM_TOTAL);
    mlp_main<<<(npts / TILE_M) * (N_C / CH_PER_CTA), 256, SMEM_TOTAL>>>(b1, b2, W3, b3, out);
}

// round 14
// speedup vs baseline: 1.2045x; 1.0034x over previous
#include <cuda_runtime.h>
#include <cuda_fp16.h>
#include <cstdint>

#define N_C    16
#define DIN    1024
#define HID    128
#define TILE_M 128
#define KC     64
#define NCHUNK (DIN / KC)   // 16
#define CH_PER_CTA 4

// ---------------- device scratch ----------------
__device__ __align__(1024) __half g_xh [67108864];        // 65536*1024 fp16
__device__ __align__(1024) __half g_w1t[N_C * HID * DIN]; // [c][h][d] K-major
__device__ __align__(1024) __half g_w2t[N_C * HID * HID]; // [c][ho][hi] K-major

// ---------------- smem: 3 slots of 32KB; slot = {A @+0, B @+16K} ----------------
#define SLOT0      0u
#define SLOT1      32768u
#define SLOT2      65536u
#define OFF_B1S    98304u
#define OFF_B2S    98816u
#define OFF_W3S    99328u
#define OFF_ACC    99840u
#define SMEM_TOTAL 100352u

#define SWZ(bo) ((bo) ^ (((bo) >> 3) & 0x70))

__device__ __forceinline__ uint32_t smem_u32(const void* p) {
    uint32_t a;
    asm("{ .reg .u64 t; cvta.to.shared.u64 t, %1; cvt.u32.u64 %0, t; }" : "=r"(a) : "l"(p));
    return a;
}

// cp.async a [128 x 128B] tile into swizzled smem; 256 threads, 16B each, 4 iters
__device__ __forceinline__ void cpa_tile(uint32_t soff_abs, const char* g,
                                         int stride_bytes, int tid) {
#pragma unroll
    for (int it = 0; it < 4; ++it) {
        int u = it * 256 + tid;
        int r = u >> 3, w = u & 7;
        uint32_t d = soff_abs + SWZ((uint32_t)(r * 128 + w * 16));
        const char* src = g + (size_t)r * stride_bytes + w * 16;
        asm volatile("cp.async.cg.shared.global [%0], [%1], 16;" :: "r"(d), "l"(src));
    }
}
#define CPA_COMMIT() asm volatile("cp.async.commit_group;" ::: "memory")
#define CPA_WAIT(n)  asm volatile("cp.async.wait_group %0;" :: "n"(n) : "memory")

__device__ __forceinline__ void ldmA(uint32_t addr, uint32_t* f) {
    asm volatile("ldmatrix.sync.aligned.m8n8.x4.shared.b16 {%0,%1,%2,%3}, [%4];"
                 : "=r"(f[0]), "=r"(f[1]), "=r"(f[2]), "=r"(f[3]) : "r"(addr));
}
__device__ __forceinline__ void ldmB4(uint32_t addr, uint32_t* f) {
    asm volatile("ldmatrix.sync.aligned.m8n8.x4.shared.b16 {%0,%1,%2,%3}, [%4];"
                 : "=r"(f[0]), "=r"(f[1]), "=r"(f[2]), "=r"(f[3]) : "r"(addr));
}
__device__ __forceinline__ void mma16816(float* c, const uint32_t* a, const uint32_t* b) {
    asm volatile(
        "mma.sync.aligned.m16n8k16.row.col.f32.f16.f16.f32 "
        "{%0,%1,%2,%3}, {%4,%5,%6,%7}, {%8,%9}, {%0,%1,%2,%3};"
        : "+f"(c[0]), "+f"(c[1]), "+f"(c[2]), "+f"(c[3])
        : "r"(a[0]), "r"(a[1]), "r"(a[2]), "r"(a[3]), "r"(b[0]), "r"(b[1]));
}

__device__ __forceinline__ uint32_t b4_addr(uint32_t sB, int ks, int q, int lane, int wn) {
    int grp = lane >> 3;
    int row = wn * 32 + (2 * q + (grp >> 1)) * 8 + (lane & 7);
    uint32_t bo = (uint32_t)(row * 128 + ks * 32 + ((grp & 1) << 4));
    return sB + SWZ(bo);
}

// one 64-wide K chunk: A [128x64] at sA, B [128x64] at sB
__device__ __forceinline__ void gemm64(uint32_t sA, uint32_t sB,
                                       float acc[4][4][4], int lane, int wm, int wn) {
#pragma unroll
    for (int ks = 0; ks < 4; ++ks) {
        uint32_t a[4][4], b[4][2];
#pragma unroll
        for (int mt = 0; mt < 4; ++mt) {
            int row = wm * 64 + mt * 16 + (lane & 15);
            uint32_t bo = (uint32_t)(row * 128 + ks * 32 + ((lane >> 4) << 4));
            ldmA(sA + SWZ(bo), a[mt]);
        }
#pragma unroll
        for (int q = 0; q < 2; ++q)
            ldmB4(b4_addr(sB, ks, q, lane, wn), &b[2 * q][0]);
#pragma unroll
        for (int mt = 0; mt < 4; ++mt)
#pragma unroll
            for (int nt = 0; nt < 4; ++nt)
                mma16816(acc[mt][nt], a[mt], b[nt]);
    }
}

// ---------------- merged prep kernel: x -> fp16 + W transposes ----------------
__global__ void prep_all(const float* __restrict__ x, const float* __restrict__ W1,
                         const float* __restrict__ W2, int xblocks) {
    if ((int)blockIdx.x < xblocks) {
        int i = blockIdx.x * 256 + threadIdx.x;
        float4 v = ((const float4*)x)[i];
        __half2* o = (__half2*)g_xh;
        o[2 * i]     = __floats2half2_rn(v.x, v.y);
        o[2 * i + 1] = __floats2half2_rn(v.z, v.w);
    } else {
        int i = (blockIdx.x - xblocks) * 256 + threadIdx.x;
        const int n1 = N_C * DIN * HID;
        if (i < n1) {
            int c = i / (DIN * HID);
            int rem = i % (DIN * HID);
            int h = rem / DIN;
            int d = rem % DIN;
            g_w1t[i] = __float2half_rn(W1[(c * DIN + d) * HID + h]);
        } else {
            int k = i - n1;
            if (k < N_C * HID * HID) {
                int c = k / (HID * HID);
                int rem = k % (HID * HID);
                int ho = rem / HID;
                int hi = rem % HID;
                g_w2t[k] = __float2half_rn(W2[(c * HID + hi) * HID + ho]);
            }
        }
    }
}

// ---------------- main fused MLP kernel (4 channels per CTA) ----------------
__global__ void __launch_bounds__(256, 2) mlp_main(
    const float* __restrict__ b1, const float* __restrict__ b2,
    const float* __restrict__ W3, const float* __restrict__ b3,
    float* __restrict__ out) {
    extern __shared__ char smem[];
    const uint32_t sbase = smem_u32(smem);
    const int tid  = threadIdx.x;
    const int lane = tid & 31;
    const int wid  = tid >> 5;
    const int wm   = wid >> 2;
    const int wn   = wid & 3;
    const int row0 = (blockIdx.x >> 2) * TILE_M;
    const int c0   = (blockIdx.x & 3) * CH_PER_CTA;

    float* b1s    = (float*)(smem + OFF_B1S);
    float* b2s    = (float*)(smem + OFF_B2S);
    float* w3s    = (float*)(smem + OFF_W3S);
    float* rowacc = (float*)(smem + OFF_ACC);

    float acc[4][4][4];
    const char* xg = (const char*)(g_xh + (size_t)row0 * DIN);

    // prologue: first channel chunks 0,1 -> SLOT0, SLOT1 (two groups)
    {
        const char* w1c = (const char*)(g_w1t + (size_t)c0 * HID * DIN);
        cpa_tile(sbase + SLOT0, xg, DIN * 2, tid);
        cpa_tile(sbase + SLOT0 + 16384u, w1c, DIN * 2, tid);
        CPA_COMMIT();
        cpa_tile(sbase + SLOT1, xg + (size_t)KC * 2, DIN * 2, tid);
        cpa_tile(sbase + SLOT1 + 16384u, w1c + (size_t)KC * 2, DIN * 2, tid);
        CPA_COMMIT();
    }

#pragma unroll 1
    for (int cc = 0; cc < CH_PER_CTA; ++cc) {
        const int c = c0 + cc;
        if (tid < HID) {
            b1s[tid] = b1[c * HID + tid];
            b2s[tid] = b2[c * HID + tid];
            w3s[tid] = W3[c * HID + tid];
            rowacc[tid] = 0.f;
        }
#pragma unroll
        for (int mt = 0; mt < 4; ++mt)
#pragma unroll
            for (int nt = 0; nt < 4; ++nt)
#pragma unroll
                for (int i = 0; i < 4; ++i) acc[mt][nt][i] = 0.f;

        const char* w1c = (const char*)(g_w1t + (size_t)c * HID * DIN);

        // ==== GEMM1: 3-slot ring, ONE barrier per chunk ====
        // invariant @ iter j top: groups pending = {j, j+1}; chunk k lives in slot k%3
        // order: wait(own j) -> barrier (j visible + gemm j-1 drained) ->
        //        issue j+2 into slot (j+2)%3 (== slot of gemm j-1, provably free) -> gemm j
        {
            uint32_t sl0 = SLOT0, sl1 = SLOT1, sl2 = SLOT2;
#pragma unroll 1
            for (int j = 0; j < NCHUNK; ++j) {
                if (j < NCHUNK - 1) CPA_WAIT(1); else CPA_WAIT(0);
                __syncthreads();
                if (j < NCHUNK - 2) {
                    cpa_tile(sbase + sl2, xg + (size_t)(j + 2) * KC * 2, DIN * 2, tid);
                    cpa_tile(sbase + sl2 + 16384u, w1c + (size_t)(j + 2) * KC * 2,
                             DIN * 2, tid);
                    CPA_COMMIT();
                }
                gemm64(sbase + sl0, sbase + sl0 + 16384u, acc, lane, wm, wn);
                uint32_t t = sl0; sl0 = sl1; sl1 = sl2; sl2 = t;
            }
        }
        __syncthreads();   // gemm 15 drained everywhere; all 6 regions free

        // one group: W2 -> SLOT1{A,B}; next channel chunk0 -> SLOT0{A,B}
        {
            const char* w2c = (const char*)(g_w2t + (size_t)c * HID * HID);
            cpa_tile(sbase + SLOT1,           w2c,                    HID * 2, tid);
            cpa_tile(sbase + SLOT1 + 16384u,  w2c + (size_t)KC * 2,   HID * 2, tid);
            if (cc < CH_PER_CTA - 1) {
                const char* w1n = (const char*)(g_w1t + (size_t)(c + 1) * HID * DIN);
                cpa_tile(sbase + SLOT0,          xg,  DIN * 2, tid);
                cpa_tile(sbase + SLOT0 + 16384u, w1n, DIN * 2, tid);
            }
            CPA_COMMIT();
        }

        // ==== epilogue 1: relu(acc + b1) -> fp16 h1 into SLOT2 {c0 @+0, c1 @+16K} ====
#pragma unroll
        for (int mt = 0; mt < 4; ++mt) {
            int r1 = wm * 64 + mt * 16 + (lane >> 2);
#pragma unroll
            for (int nt = 0; nt < 4; ++nt) {
                int n = wn * 32 + nt * 8 + (lane & 3) * 2;
                uint32_t chb = SLOT2 + (uint32_t)(n >> 6) * 16384u;
                uint32_t nc = (uint32_t)(n & 63);
                float* cc2 = acc[mt][nt];
                __half2 h0 = __floats2half2_rn(fmaxf(cc2[0] + b1s[n], 0.f),
                                               fmaxf(cc2[1] + b1s[n + 1], 0.f));
                __half2 h1v = __floats2half2_rn(fmaxf(cc2[2] + b1s[n], 0.f),
                                                fmaxf(cc2[3] + b1s[n + 1], 0.f));
                *(__half2*)(smem + chb + SWZ((uint32_t)r1 * 128u + nc * 2u)) = h0;
                *(__half2*)(smem + chb + SWZ((uint32_t)(r1 + 8) * 128u + nc * 2u)) = h1v;
            }
        }
        CPA_WAIT(0);
        __syncthreads();   // h1 (STS) + W2/chunk0 (cp.async) visible

        // ==== GEMM2: A = h1 (SLOT2), B = W2 (SLOT1) ====
#pragma unroll
        for (int mt = 0; mt < 4; ++mt)
#pragma unroll
            for (int nt = 0; nt < 4; ++nt)
#pragma unroll
                for (int i = 0; i < 4; ++i) acc[mt][nt][i] = 0.f;

        gemm64(sbase + SLOT2,           sbase + SLOT1,           acc, lane, wm, wn);
        gemm64(sbase + SLOT2 + 16384u,  sbase + SLOT1 + 16384u,  acc, lane, wm, wn);
        __syncthreads();   // GEMM2 drained; SLOT1 reusable

        // next channel chunk1 -> SLOT1{A,B} — overlaps epilogue 2
        if (cc < CH_PER_CTA - 1) {
            const char* w1n = (const char*)(g_w1t + (size_t)(c + 1) * HID * DIN);
            cpa_tile(sbase + SLOT1,          xg  + (size_t)KC * 2, DIN * 2, tid);
            cpa_tile(sbase + SLOT1 + 16384u, w1n + (size_t)KC * 2, DIN * 2, tid);
            CPA_COMMIT();
        }

        // ==== epilogue 2: out = relu(acc + b2) . W3 + b3 ====
#pragma unroll
        for (int mt = 0; mt < 4; ++mt) {
            float p1 = 0.f, p2 = 0.f;
#pragma unroll
            for (int nt = 0; nt < 4; ++nt) {
                int n = wn * 32 + nt * 8 + (lane & 3) * 2;
                float* cc2 = acc[mt][nt];
                float w0 = w3s[n], w1v = w3s[n + 1];
                float c2a = b2s[n], c2b = b2s[n + 1];
                p1 += fmaxf(cc2[0] + c2a, 0.f) * w0 + fmaxf(cc2[1] + c2b, 0.f) * w1v;
                p2 += fmaxf(cc2[2] + c2a, 0.f) * w0 + fmaxf(cc2[3] + c2b, 0.f) * w1v;
            }
            p1 += __shfl_xor_sync(0xFFFFFFFFu, p1, 1);
            p1 += __shfl_xor_sync(0xFFFFFFFFu, p1, 2);
            p2 += __shfl_xor_sync(0xFFFFFFFFu, p2, 1);
            p2 += __shfl_xor_sync(0xFFFFFFFFu, p2, 2);
            if ((lane & 3) == 0) {
                int r = wm * 64 + mt * 16 + (lane >> 2);
                atomicAdd(&rowacc[r], p1);
                atomicAdd(&rowacc[r + 8], p2);
            }
        }
        __syncthreads();
        if (tid < TILE_M)
            out[(size_t)(row0 + tid) * N_C + c] = rowacc[tid] + b3[c];
        __syncthreads();   // protect smem vectors before next channel rewrites
    }
}

// ---------------- launch ----------------
extern "C" void kernel_launch(void* const* d_in, const int* in_sizes, int n_in,
                              void* d_out, int out_size) {
    const float* x  = (const float*)d_in[0];
    const float* W1 = (const float*)d_in[1];
    const float* b1 = (const float*)d_in[2];
    const float* W2 = (const float*)d_in[3];
    const float* b2 = (const float*)d_in[4];
    const float* W3 = (const float*)d_in[5];
    const float* b3 = (const float*)d_in[6];
    float* out = (float*)d_out;

    const int npts = in_sizes[0] / DIN;               // 65536
    const int xblocks = npts * (DIN / 4) / 256;       // 65536
    const int wtot = N_C * DIN * HID + N_C * HID * HID;
    const int wblocks = (wtot + 255) / 256;

    prep_all<<<xblocks + wblocks, 256>>>(x, W1, W2, xblocks);

    cudaFuncSetAttribute(mlp_main, cudaFuncAttributeMaxDynamicSharedMemorySize, SMEM_TOTAL);
    mlp_main<<<(npts / TILE_M) * (N_C / CH_PER_CTA), 256, SMEM_TOTAL>>>(b1, b2, W3, b3, out);
}